// round 9
// baseline (speedup 1.0000x reference)
#include <cuda_runtime.h>
#include <cuda_fp16.h>
#include <cstdint>

#define N_NODES 40000
#define N_EDGES 640000
#define D_FEAT  128

// ---------------------------------------------------------------------------
// Scratch (allocation-free: __device__ globals)
// g_fh4 aligned to 256 B so 32 B (v8.b32) accesses are always aligned.
// ---------------------------------------------------------------------------
__device__ __align__(256) uint4 g_fh4[N_NODES * D_FEAT / 8]; // fp16 feats (10.2 MB)
__device__ float              g_ee[N_EDGES];                 // exp(e) per edge
__device__ unsigned long long g_sum[N_NODES];                // fixed-point 2^32 sums

// ---------------------------------------------------------------------------
// 256-bit load/store helpers (sm_100+: .v8.b32)
// ---------------------------------------------------------------------------
__device__ __forceinline__ void ldg256(const void* p, uint32_t* r) {
    asm volatile("ld.global.nc.v8.b32 {%0,%1,%2,%3,%4,%5,%6,%7}, [%8];"
                 : "=r"(r[0]), "=r"(r[1]), "=r"(r[2]), "=r"(r[3]),
                   "=r"(r[4]), "=r"(r[5]), "=r"(r[6]), "=r"(r[7])
                 : "l"(p));
}
__device__ __forceinline__ void stg256(void* p, const uint32_t* r) {
    asm volatile("st.global.v8.b32 [%0], {%1,%2,%3,%4,%5,%6,%7,%8};"
                 :: "l"(p),
                    "r"(r[0]), "r"(r[1]), "r"(r[2]), "r"(r[3]),
                    "r"(r[4]), "r"(r[5]), "r"(r[6]), "r"(r[7])
                 : "memory");
}

// ---------------------------------------------------------------------------
// K1: convert feats fp32 -> fp16 + zero g_sum.
// Thread i handles 16 consecutive floats: 2 x LDG.256 -> 1 x STG.256 (32 B fp16).
// ---------------------------------------------------------------------------
__global__ __launch_bounds__(256) void convert_kernel(const float* __restrict__ feats) {
    int i = blockIdx.x * blockDim.x + threadIdx.x;     // [0, 320000)

    uint32_t v[16];
    ldg256(feats + i * 16,     v);
    ldg256(feats + i * 16 + 8, v + 8);

    uint32_t h[8];
    const float* f = (const float*)v;
#pragma unroll
    for (int j = 0; j < 8; j++) {
        __half2 hh = __floats2half2_rn(f[2 * j], f[2 * j + 1]);
        h[j] = *(const uint32_t*)&hh;
    }
    stg256((char*)g_fh4 + (size_t)i * 32, h);

    if (i < N_NODES) g_sum[i] = 0ULL;
}

// ---------------------------------------------------------------------------
// K2: 8 lanes per edge (4 edges/warp).
// Row = 256 B = 8 x 32 B chunks. Lane l does ONE LDG.256 on chunk l of the src
// row and one on the dst row (2 loads/thread, fully coalesced).
//   e  = exp(-0.01 * L1)  in (0, 1]
//   ee = exp(e)           in (1, 2.72]  (segment-max pass mathematically moot)
// Leader lane stores ee, accumulates fixed-point ee to g_sum[dst]
// (u64 integer atomics are associative -> deterministic).
// ---------------------------------------------------------------------------
__global__ __launch_bounds__(256) void edge_kernel(const int* __restrict__ src,
                                                   const int* __restrict__ dst) {
    int t    = blockIdx.x * blockDim.x + threadIdx.x;
    int edge = t >> 3;
    int lane = t & 7;
    if (edge >= N_EDGES) return;

    int s = src[edge];                    // broadcast within 8-group
    int d = dst[edge];

    const char* base = (const char*)g_fh4;
    uint32_t a[8], b[8];
    ldg256(base + (size_t)s * 256 + lane * 32, a);
    ldg256(base + (size_t)d * 256 + lane * 32, b);

    float acc = 0.0f;
#pragma unroll
    for (int j = 0; j < 8; j++) {
        __half2 ha = *(const __half2*)&a[j];
        __half2 hb = *(const __half2*)&b[j];
        __half2 dd = __habs2(__hsub2(ha, hb));
        float2 f = __half22float2(dd);
        acc += f.x + f.y;
    }

    acc += __shfl_xor_sync(0xffffffffu, acc, 4);
    acc += __shfl_xor_sync(0xffffffffu, acc, 2);
    acc += __shfl_xor_sync(0xffffffffu, acc, 1);

    if (lane == 0) {
        float e  = __expf(-0.01f * acc);
        float ee = __expf(e);
        g_ee[edge] = ee;
        unsigned long long q = (unsigned long long)(ee * 4294967296.0f);
        atomicAdd(&g_sum[d], q);
    }
}

// ---------------------------------------------------------------------------
// K3: out[i] = ee[i] / sum[dst[i]], 4 edges per thread (vectorized).
// ---------------------------------------------------------------------------
__global__ __launch_bounds__(256) void finalize_kernel(const int4* __restrict__ dst4,
                                                       float4* __restrict__ out4) {
    int i = blockIdx.x * blockDim.x + threadIdx.x;     // [0, 160000)
    if (i < N_EDGES / 4) {
        int4   d = dst4[i];
        float4 e = ((const float4*)g_ee)[i];
        float4 r;
        r.x = __fdividef(e.x, (float)g_sum[d.x] * 0x1p-32f);
        r.y = __fdividef(e.y, (float)g_sum[d.y] * 0x1p-32f);
        r.z = __fdividef(e.z, (float)g_sum[d.z] * 0x1p-32f);
        r.w = __fdividef(e.w, (float)g_sum[d.w] * 0x1p-32f);
        out4[i] = r;
    }
}

// ---------------------------------------------------------------------------
extern "C" void kernel_launch(void* const* d_in, const int* in_sizes, int n_in,
                              void* d_out, int out_size) {
    const float* feats = (const float*)d_in[0];
    const int*   src   = (const int*)d_in[1];
    const int*   dst   = (const int*)d_in[2];
    float*       out   = (float*)d_out;

    // 320000 threads, each converts 16 floats
    convert_kernel<<<(N_NODES * D_FEAT / 16) / 256, 256>>>(feats);

    // 8 lanes per edge: 640000 * 8 = 5.12M threads
    edge_kernel<<<(N_EDGES * 8) / 256, 256>>>(src, dst);

    finalize_kernel<<<(N_EDGES / 4 + 255) / 256, 256>>>((const int4*)dst,
                                                        (float4*)out);
}

// round 10
// speedup vs baseline: 1.0667x; 1.0667x over previous
#include <cuda_runtime.h>
#include <cuda_fp16.h>
#include <cstdint>

#define N_NODES 40000
#define N_EDGES 640000
#define D_FEAT  128

// ---------------------------------------------------------------------------
// Scratch (allocation-free: __device__ globals)
// g_fh4 aligned 256 B so 32 B (v8.b32) accesses are always aligned.
// ---------------------------------------------------------------------------
__device__ __align__(256) uint4 g_fh4[N_NODES * D_FEAT / 8]; // fp16 feats (10.2 MB)
__device__ float              g_ee[N_EDGES];                 // exp(e) per edge
__device__ unsigned long long g_sum[N_NODES];                // fixed-point 2^32 sums

// ---------------------------------------------------------------------------
// 256-bit load/store helpers (sm_100+: .v8.b32)
// ---------------------------------------------------------------------------
__device__ __forceinline__ void ldg256(const void* p, uint32_t* r) {
    asm volatile("ld.global.nc.v8.b32 {%0,%1,%2,%3,%4,%5,%6,%7}, [%8];"
                 : "=r"(r[0]), "=r"(r[1]), "=r"(r[2]), "=r"(r[3]),
                   "=r"(r[4]), "=r"(r[5]), "=r"(r[6]), "=r"(r[7])
                 : "l"(p));
}
__device__ __forceinline__ void stg256(void* p, const uint32_t* r) {
    asm volatile("st.global.v8.b32 [%0], {%1,%2,%3,%4,%5,%6,%7,%8};"
                 :: "l"(p),
                    "r"(r[0]), "r"(r[1]), "r"(r[2]), "r"(r[3]),
                    "r"(r[4]), "r"(r[5]), "r"(r[6]), "r"(r[7])
                 : "memory");
}

// ---------------------------------------------------------------------------
// K1: convert feats fp32 -> fp16 + zero g_sum.
// Thread i handles 16 consecutive floats: 2 x LDG.256 -> 1 x STG.256.
// (Shape proven insensitive: DRAM-read bound at ~2.7 TB/s.)
// ---------------------------------------------------------------------------
__global__ __launch_bounds__(256) void convert_kernel(const float* __restrict__ feats) {
    int i = blockIdx.x * blockDim.x + threadIdx.x;     // [0, 320000)

    uint32_t v[16];
    ldg256(feats + i * 16,     v);
    ldg256(feats + i * 16 + 8, v + 8);

    uint32_t h[8];
    const float* f = (const float*)v;
#pragma unroll
    for (int j = 0; j < 8; j++) {
        __half2 hh = __floats2half2_rn(f[2 * j], f[2 * j + 1]);
        h[j] = *(const uint32_t*)&hh;
    }
    stg256((char*)g_fh4 + (size_t)i * 32, h);

    if (i < N_NODES) g_sum[i] = 0ULL;
}

// ---------------------------------------------------------------------------
// K2: 4 lanes per edge (8 edges/warp).
// Row = 256 B. Lane l loads 32 B chunks l and l+4 of both rows:
// 4 independent front-batched LDG.256 per thread, 128 B coalesced segments.
//   e  = exp(-0.01 * L1)  in (0, 1]
//   ee = exp(e)           in (1, 2.72]   (segment-max pass mathematically moot)
// Leader lane stores ee and adds fixed-point ee to g_sum[dst]
// (u64 integer atomics are associative -> deterministic).
// ---------------------------------------------------------------------------
__global__ __launch_bounds__(256) void edge_kernel(const int* __restrict__ src,
                                                   const int* __restrict__ dst) {
    int t    = blockIdx.x * blockDim.x + threadIdx.x;
    int edge = t >> 2;
    int lane = t & 3;
    if (edge >= N_EDGES) return;

    int s = src[edge];                    // broadcast within 4-group
    int d = dst[edge];

    const char* base = (const char*)g_fh4;
    uint32_t a0[8], a1[8], b0[8], b1[8];
    ldg256(base + (size_t)s * 256 +       lane * 32, a0);
    ldg256(base + (size_t)s * 256 + 128 + lane * 32, a1);
    ldg256(base + (size_t)d * 256 +       lane * 32, b0);
    ldg256(base + (size_t)d * 256 + 128 + lane * 32, b1);

    float acc = 0.0f;
#pragma unroll
    for (int j = 0; j < 8; j++) {
        __half2 d0 = __habs2(__hsub2(*(const __half2*)&a0[j], *(const __half2*)&b0[j]));
        __half2 d1 = __habs2(__hsub2(*(const __half2*)&a1[j], *(const __half2*)&b1[j]));
        float2 f0 = __half22float2(d0);
        float2 f1 = __half22float2(d1);
        acc += (f0.x + f0.y) + (f1.x + f1.y);
    }

    acc += __shfl_xor_sync(0xffffffffu, acc, 2);
    acc += __shfl_xor_sync(0xffffffffu, acc, 1);

    if (lane == 0) {
        float e  = __expf(-0.01f * acc);
        float ee = __expf(e);
        g_ee[edge] = ee;
        unsigned long long q = (unsigned long long)(ee * 4294967296.0f);
        atomicAdd(&g_sum[d], q);
    }
}

// ---------------------------------------------------------------------------
// K3: out[i] = ee[i] / sum[dst[i]], 4 edges per thread (vectorized).
// ---------------------------------------------------------------------------
__global__ __launch_bounds__(256) void finalize_kernel(const int4* __restrict__ dst4,
                                                       float4* __restrict__ out4) {
    int i = blockIdx.x * blockDim.x + threadIdx.x;     // [0, 160000)
    if (i < N_EDGES / 4) {
        int4   d = dst4[i];
        float4 e = ((const float4*)g_ee)[i];
        float4 r;
        r.x = __fdividef(e.x, (float)g_sum[d.x] * 0x1p-32f);
        r.y = __fdividef(e.y, (float)g_sum[d.y] * 0x1p-32f);
        r.z = __fdividef(e.z, (float)g_sum[d.z] * 0x1p-32f);
        r.w = __fdividef(e.w, (float)g_sum[d.w] * 0x1p-32f);
        out4[i] = r;
    }
}

// ---------------------------------------------------------------------------
extern "C" void kernel_launch(void* const* d_in, const int* in_sizes, int n_in,
                              void* d_out, int out_size) {
    const float* feats = (const float*)d_in[0];
    const int*   src   = (const int*)d_in[1];
    const int*   dst   = (const int*)d_in[2];
    float*       out   = (float*)d_out;

    // 320000 threads, each converts 16 floats
    convert_kernel<<<(N_NODES * D_FEAT / 16) / 256, 256>>>(feats);

    // 4 lanes per edge: 640000 * 4 = 2.56M threads
    edge_kernel<<<(N_EDGES * 4) / 256, 256>>>(src, dst);

    finalize_kernel<<<(N_EDGES / 4 + 255) / 256, 256>>>((const int4*)dst,
                                                        (float4*)out);
}